// round 2
// baseline (speedup 1.0000x reference)
#include <cuda_runtime.h>
#include <math.h>

#define IMG 1024
#define NPATCH 16384

__global__ __launch_bounds__(128)
void curvature_kernel(const float* __restrict__ depth, float* __restrict__ out)
{
    int idx = blockIdx.x * blockDim.x + threadIdx.x;
    if (idx >= NPATCH) return;
    const int pi = idx >> 7;    // patch row  (oh)
    const int pj = idx & 127;   // patch col  (ow)

    // center point = unfold index 36 = (r=4,c=4): padded (8i+4, 8j+4) -> orig (8i+3, 8j+3)
    const int yc = 8 * pi + 3, xc = 8 * pj + 3;
    const float d36 = __ldg(&depth[yc * IMG + xc]);
    const float x36 = (float)xc, y36 = (float)yc;

    // ---- accumulate scatter blocks in fp64 ----
    double T00=0,T01=0,T02=0,T11=0,T12=0,T22=0;  // T = sum l l^T, l=(2p1,2p2,2p3)
    double E[18];                                 // E[f*3+m] = sum d_f * l_m
    double S[21];                                 // upper tri of S11 = sum d d^T
    #pragma unroll
    for (int t = 0; t < 18; t++) E[t] = 0.0;
    #pragma unroll
    for (int t = 0; t < 21; t++) S[t] = 0.0;

    #pragma unroll 1
    for (int r = 0; r < 8; r++) {
        const int R = 8 * pi + r;                 // padded row
        #pragma unroll
        for (int c = 0; c < 8; c++) {
            const int C = 8 * pj + c;             // padded col
            float xv, yv, dv;
            if (R == 0 || C == 0) { xv = 0.f; yv = 0.f; dv = 0.f; }  // zero pad
            else {
                xv = (float)(C - 1);
                yv = (float)(R - 1);
                dv = __ldg(&depth[(R - 1) * IMG + (C - 1)]);
            }
            const float f1 = xv - x36, f2 = yv - y36, f3 = dv - d36;  // fp32 like ref
            const double p1 = f1, p2 = f2, p3 = f3;
            double dd[6];
            dd[0] = p1 * p1; dd[1] = p2 * p2; dd[2] = p3 * p3;
            dd[3] = 2.0 * p1 * p2; dd[4] = 2.0 * p1 * p3; dd[5] = 2.0 * p2 * p3;
            const double l0 = 2.0 * p1, l1 = 2.0 * p2, l2 = 2.0 * p3;
            int t = 0;
            #pragma unroll
            for (int f = 0; f < 6; f++) {
                #pragma unroll
                for (int g = f; g < 6; g++) { S[t] += dd[f] * dd[g]; t++; }
            }
            #pragma unroll
            for (int f = 0; f < 6; f++) {
                E[f * 3 + 0] += dd[f] * l0;
                E[f * 3 + 1] += dd[f] * l1;
                E[f * 3 + 2] += dd[f] * l2;
            }
            T00 += l0 * l0; T01 += l0 * l1; T02 += l0 * l2;
            T11 += l1 * l1; T12 += l1 * l2; T22 += l2 * l2;
        }
    }

    // ---- T^{-1} (3x3 symmetric) ----
    const double c00 = T11 * T22 - T12 * T12;
    const double c01 = T02 * T12 - T01 * T22;
    const double c02 = T01 * T12 - T02 * T11;
    const double det = T00 * c00 + T01 * c01 + T02 * c02;
    const double id = 1.0 / det;
    const double I00 = c00 * id, I01 = c01 * id, I02 = c02 * id;
    const double I11 = (T00 * T22 - T02 * T02) * id;
    const double I12 = (T01 * T02 - T00 * T12) * id;
    const double I22 = (T00 * T11 - T01 * T01) * id;

    // ---- A = S11 - E T^{-1} E^T  (6x6 symmetric) ----
    double a[36];
    {
        int t = 0;
        #pragma unroll
        for (int f = 0; f < 6; f++) {
            const double e0 = E[f * 3 + 0], e1 = E[f * 3 + 1], e2 = E[f * 3 + 2];
            const double w0 = e0 * I00 + e1 * I01 + e2 * I02;
            const double w1 = e0 * I01 + e1 * I11 + e2 * I12;
            const double w2 = e0 * I02 + e1 * I12 + e2 * I22;
            #pragma unroll
            for (int g = f; g < 6; g++) {
                const double v = S[t] - (w0 * E[g * 3 + 0] + w1 * E[g * 3 + 1] + w2 * E[g * 3 + 2]);
                a[f * 6 + g] = v; a[g * 6 + f] = v; t++;
            }
        }
    }
    const double tr = a[0] + a[7] + a[14] + a[21] + a[28] + a[35];

    // ---- Cholesky A = L L^T ----
    double L[36];
    #pragma unroll
    for (int t = 0; t < 36; t++) L[t] = 0.0;
    #pragma unroll
    for (int k = 0; k < 6; k++) {
        double s = a[k * 6 + k];
        #pragma unroll
        for (int m = 0; m < k; m++) s -= L[k * 6 + m] * L[k * 6 + m];
        s = fmax(s, fabs(tr) * 1e-13 + 1e-300);
        const double dk = sqrt(s);
        const double inv = 1.0 / dk;
        L[k * 6 + k] = dk;
        #pragma unroll
        for (int r2 = k + 1; r2 < 6; r2++) {
            double sv = a[r2 * 6 + k];
            #pragma unroll
            for (int m = 0; m < k; m++) sv -= L[r2 * 6 + m] * L[k * 6 + m];
            L[r2 * 6 + k] = sv * inv;
        }
    }

    // ---- G = L^T Cinv L  (symmetric 6x6);  Cinv = [[0,.5,.5],[.5,0,.5],[.5,.5,0]] (+) -0.25*I3 ----
    double g[36];
    {
        double Y[36];
        #pragma unroll
        for (int j = 0; j < 6; j++) {
            Y[0 * 6 + j] = 0.5 * (L[6 + j] + L[12 + j]);
            Y[1 * 6 + j] = 0.5 * (L[0 + j] + L[12 + j]);
            Y[2 * 6 + j] = 0.5 * (L[0 + j] + L[6 + j]);
            Y[3 * 6 + j] = -0.25 * L[18 + j];
            Y[4 * 6 + j] = -0.25 * L[24 + j];
            Y[5 * 6 + j] = -0.25 * L[30 + j];
        }
        #pragma unroll
        for (int i2 = 0; i2 < 6; i2++) {
            #pragma unroll
            for (int j = 0; j < 6; j++) {
                double sv = 0.0;
                #pragma unroll
                for (int k = 0; k < 6; k++) sv += L[k * 6 + i2] * Y[k * 6 + j];
                g[i2 * 6 + j] = sv;
            }
        }
    }

    // ---- cyclic Jacobi eigensolver on G with eigenvector accumulation ----
    double U[36];
    #pragma unroll
    for (int t = 0; t < 36; t++) U[t] = (t % 7 == 0) ? 1.0 : 0.0;

    const int PP[15] = {0,0,0,0,0,1,1,1,1,2,2,2,3,3,4};
    const int QQ[15] = {1,2,3,4,5,2,3,4,5,3,4,5,4,5,5};
    #pragma unroll 1
    for (int sweep = 0; sweep < 8; sweep++) {
        #pragma unroll
        for (int t = 0; t < 15; t++) {
            const int p = PP[t], q = QQ[t];
            const double apq = g[p * 6 + q];
            if (fabs(apq) > 1e-150) {
                const double app = g[p * 6 + p], aqq = g[q * 6 + q];
                const double theta = (aqq - app) / (2.0 * apq);
                const double tt = copysign(1.0, theta) / (fabs(theta) + sqrt(1.0 + theta * theta));
                const double cph = rsqrt(1.0 + tt * tt);
                const double sph = tt * cph;
                #pragma unroll
                for (int k = 0; k < 6; k++) {
                    const double gkp = g[k * 6 + p], gkq = g[k * 6 + q];
                    g[k * 6 + p] = cph * gkp - sph * gkq;
                    g[k * 6 + q] = sph * gkp + cph * gkq;
                }
                #pragma unroll
                for (int k = 0; k < 6; k++) {
                    const double gpk = g[p * 6 + k], gqk = g[q * 6 + k];
                    g[p * 6 + k] = cph * gpk - sph * gqk;
                    g[q * 6 + k] = sph * gpk + cph * gqk;
                }
                #pragma unroll
                for (int k = 0; k < 6; k++) {
                    const double ukp = U[k * 6 + p], ukq = U[k * 6 + q];
                    U[k * 6 + p] = cph * ukp - sph * ukq;
                    U[k * 6 + q] = sph * ukp + cph * ukq;
                }
            }
        }
    }

    // ---- pick eigenvector of the max (unique positive) eigenvalue ----
    int bi = 0; double best = g[0];
    #pragma unroll
    for (int d2 = 1; d2 < 6; d2++) {
        const double dv2 = g[d2 * 6 + d2];
        if (dv2 > best) { best = dv2; bi = d2; }
    }
    double u[6];
    #pragma unroll
    for (int k = 0; k < 6; k++) {
        double val = U[k * 6 + 0];
        #pragma unroll
        for (int d2 = 1; d2 < 6; d2++) val = (bi == d2) ? U[k * 6 + d2] : val;
        u[k] = val;
    }

    // ---- solve L^T v = u (back substitution) -> vecs1 ----
    double v[6];
    #pragma unroll
    for (int k = 5; k >= 0; k--) {
        double s = u[k];
        #pragma unroll
        for (int m = 5; m > k; m--) s -= L[m * 6 + k] * v[m];
        v[k] = s / L[k * 6 + k];
    }

    // ---- Q = [[v0,v3,v4],[v3,v1,v5],[v4,v5,v2]]; closed-form symmetric 3x3 eigenvalues ----
    const double qa = v[0], qb = v[1], qc = v[2], qd = v[3], qe = v[4], qf = v[5];
    double l1, l2, l3;
    const double off2 = qd * qd + qe * qe + qf * qf;
    if (off2 < 1e-300) { l1 = qa; l2 = qb; l3 = qc; }
    else {
        const double qm = (qa + qb + qc) / 3.0;
        const double aa = qa - qm, bb = qb - qm, cc = qc - qm;
        const double p2 = aa * aa + bb * bb + cc * cc + 2.0 * off2;
        const double p = sqrt(p2 / 6.0);
        const double ip = 1.0 / p;
        const double b00 = aa * ip, b11 = bb * ip, b22 = cc * ip;
        const double b01 = qd * ip, b02 = qe * ip, b12 = qf * ip;
        double detB = b00 * (b11 * b22 - b12 * b12)
                    - b01 * (b01 * b22 - b12 * b02)
                    + b02 * (b01 * b12 - b11 * b02);
        double rr = 0.5 * detB;
        rr = fmin(1.0, fmax(-1.0, rr));
        const double phi = acos(rr) / 3.0;
        l1 = qm + 2.0 * p * cos(phi);
        l3 = qm + 2.0 * p * cos(phi + 2.0943951023931953);  // + 2*pi/3
        l2 = 3.0 * qm - l1 - l3;
    }
    const double a1 = fabs(l1), a2 = fabs(l2), a3 = fabs(l3);
    const double mx = fmax(a1, fmax(a2, a3));
    const double mn = fmin(a1, fmin(a2, a3));
    // simi = min(radii)/max(radii) = sqrt(min|lam| / max|lam|)  (R33-scale cancels)
    out[idx] = (float)sqrt(mn / mx);
}

extern "C" void kernel_launch(void* const* d_in, const int* in_sizes, int n_in,
                              void* d_out, int out_size)
{
    const float* depth = (const float*)d_in[0];
    float* out = (float*)d_out;
    curvature_kernel<<<NPATCH / 128, 128>>>(depth, out);
}

// round 3
// speedup vs baseline: 1.3780x; 1.3780x over previous
#include <cuda_runtime.h>
#include <math.h>

#define IMG 1024
#define NPATCH 16384

// ---- common tail: given scatter blocks (fp32), produce simi ----
__device__ __forceinline__ float solve_tail(
    const float S[21], const float E[18],
    float T00, float T01, float T02, float T11, float T12, float T22)
{
    // T^{-1} (3x3 symmetric)
    const float c00 = T11 * T22 - T12 * T12;
    const float c01 = T02 * T12 - T01 * T22;
    const float c02 = T01 * T12 - T02 * T11;
    const float det = T00 * c00 + T01 * c01 + T02 * c02;
    const float id = 1.0f / det;
    const float I00 = c00 * id, I01 = c01 * id, I02 = c02 * id;
    const float I11 = (T00 * T22 - T02 * T02) * id;
    const float I12 = (T01 * T02 - T00 * T12) * id;
    const float I22 = (T00 * T11 - T01 * T01) * id;

    // A = S11 - E T^{-1} E^T  (6x6 symmetric)
    float a[36];
    {
        int t = 0;
        #pragma unroll
        for (int f = 0; f < 6; f++) {
            const float e0 = E[f * 3 + 0], e1 = E[f * 3 + 1], e2 = E[f * 3 + 2];
            const float w0 = e0 * I00 + e1 * I01 + e2 * I02;
            const float w1 = e0 * I01 + e1 * I11 + e2 * I12;
            const float w2 = e0 * I02 + e1 * I12 + e2 * I22;
            #pragma unroll
            for (int g = f; g < 6; g++) {
                const float v = S[t] - (w0 * E[g * 3 + 0] + w1 * E[g * 3 + 1] + w2 * E[g * 3 + 2]);
                a[f * 6 + g] = v; a[g * 6 + f] = v; t++;
            }
        }
    }
    const float tr = a[0] + a[7] + a[14] + a[21] + a[28] + a[35];

    // Cholesky A = L L^T
    float L[36];
    #pragma unroll
    for (int t = 0; t < 36; t++) L[t] = 0.0f;
    #pragma unroll
    for (int k = 0; k < 6; k++) {
        float s = a[k * 6 + k];
        #pragma unroll
        for (int m = 0; m < k; m++) s -= L[k * 6 + m] * L[k * 6 + m];
        s = fmaxf(s, fabsf(tr) * 1e-7f + 1e-30f);
        const float dk = sqrtf(s);
        const float inv = 1.0f / dk;
        L[k * 6 + k] = dk;
        #pragma unroll
        for (int r2 = k + 1; r2 < 6; r2++) {
            float sv = a[r2 * 6 + k];
            #pragma unroll
            for (int m = 0; m < k; m++) sv -= L[r2 * 6 + m] * L[k * 6 + m];
            L[r2 * 6 + k] = sv * inv;
        }
    }

    // G = L^T Cinv L;  Cinv = [[0,.5,.5],[.5,0,.5],[.5,.5,0]] (+) -0.25*I3
    float g[36];
    {
        float Y[36];
        #pragma unroll
        for (int j = 0; j < 6; j++) {
            Y[0 * 6 + j] = 0.5f * (L[6 + j] + L[12 + j]);
            Y[1 * 6 + j] = 0.5f * (L[0 + j] + L[12 + j]);
            Y[2 * 6 + j] = 0.5f * (L[0 + j] + L[6 + j]);
            Y[3 * 6 + j] = -0.25f * L[18 + j];
            Y[4 * 6 + j] = -0.25f * L[24 + j];
            Y[5 * 6 + j] = -0.25f * L[30 + j];
        }
        #pragma unroll
        for (int i2 = 0; i2 < 6; i2++) {
            #pragma unroll
            for (int j = 0; j < 6; j++) {
                float sv = 0.0f;
                #pragma unroll
                for (int k = 0; k < 6; k++) sv += L[k * 6 + i2] * Y[k * 6 + j];
                g[i2 * 6 + j] = sv;
            }
        }
    }

    // cyclic Jacobi with eigenvector accumulation (6 sweeps, fp32)
    float U[36];
    #pragma unroll
    for (int t = 0; t < 36; t++) U[t] = (t % 7 == 0) ? 1.0f : 0.0f;

    #pragma unroll 1
    for (int sweep = 0; sweep < 6; sweep++) {
        #pragma unroll
        for (int t = 0; t < 15; t++) {
            const int PP[15] = {0,0,0,0,0,1,1,1,1,2,2,2,3,3,4};
            const int QQ[15] = {1,2,3,4,5,2,3,4,5,3,4,5,4,5,5};
            const int p = PP[t], q = QQ[t];
            const float apq = g[p * 6 + q];
            if (fabsf(apq) > 1e-30f) {
                const float app = g[p * 6 + p], aqq = g[q * 6 + q];
                const float theta = (aqq - app) / (2.0f * apq);
                const float tt = copysignf(1.0f, theta) / (fabsf(theta) + sqrtf(1.0f + theta * theta));
                const float cph = rsqrtf(1.0f + tt * tt);
                const float sph = tt * cph;
                #pragma unroll
                for (int k = 0; k < 6; k++) {
                    const float gkp = g[k * 6 + p], gkq = g[k * 6 + q];
                    g[k * 6 + p] = cph * gkp - sph * gkq;
                    g[k * 6 + q] = sph * gkp + cph * gkq;
                }
                #pragma unroll
                for (int k = 0; k < 6; k++) {
                    const float gpk = g[p * 6 + k], gqk = g[q * 6 + k];
                    g[p * 6 + k] = cph * gpk - sph * gqk;
                    g[q * 6 + k] = sph * gpk + cph * gqk;
                }
                #pragma unroll
                for (int k = 0; k < 6; k++) {
                    const float ukp = U[k * 6 + p], ukq = U[k * 6 + q];
                    U[k * 6 + p] = cph * ukp - sph * ukq;
                    U[k * 6 + q] = sph * ukp + cph * ukq;
                }
            }
        }
    }

    // eigenvector of the unique positive (max) eigenvalue
    int bi = 0; float best = g[0];
    #pragma unroll
    for (int d2 = 1; d2 < 6; d2++) {
        const float dv2 = g[d2 * 6 + d2];
        if (dv2 > best) { best = dv2; bi = d2; }
    }
    float u[6];
    #pragma unroll
    for (int k = 0; k < 6; k++) {
        float val = U[k * 6 + 0];
        #pragma unroll
        for (int d2 = 1; d2 < 6; d2++) val = (bi == d2) ? U[k * 6 + d2] : val;
        u[k] = val;
    }

    // back-substitution L^T v = u
    float v[6];
    #pragma unroll
    for (int k = 5; k >= 0; k--) {
        float s = u[k];
        #pragma unroll
        for (int m = 5; m > k; m--) s -= L[m * 6 + k] * v[m];
        v[k] = s / L[k * 6 + k];
    }

    // closed-form symmetric 3x3 eigenvalues of Q = [[v0,v3,v4],[v3,v1,v5],[v4,v5,v2]]
    const float qa = v[0], qb = v[1], qc = v[2], qd = v[3], qe = v[4], qf = v[5];
    float l1, l2, l3;
    const float off2 = qd * qd + qe * qe + qf * qf;
    if (off2 < 1e-30f) { l1 = qa; l2 = qb; l3 = qc; }
    else {
        const float qm = (qa + qb + qc) * (1.0f / 3.0f);
        const float aa = qa - qm, bb = qb - qm, cc = qc - qm;
        const float p2 = aa * aa + bb * bb + cc * cc + 2.0f * off2;
        const float p = sqrtf(p2 * (1.0f / 6.0f));
        const float ip = 1.0f / p;
        const float b00 = aa * ip, b11 = bb * ip, b22 = cc * ip;
        const float b01 = qd * ip, b02 = qe * ip, b12 = qf * ip;
        float detB = b00 * (b11 * b22 - b12 * b12)
                   - b01 * (b01 * b22 - b12 * b02)
                   + b02 * (b01 * b12 - b11 * b02);
        float rr = 0.5f * detB;
        rr = fminf(1.0f, fmaxf(-1.0f, rr));
        const float phi = acosf(rr) * (1.0f / 3.0f);
        l1 = qm + 2.0f * p * cosf(phi);
        l3 = qm + 2.0f * p * cosf(phi + 2.0943951023931953f);
        l2 = 3.0f * qm - l1 - l3;
    }
    const float a1 = fabsf(l1), a2 = fabsf(l2), a3 = fabsf(l3);
    const float mx = fmaxf(a1, fmaxf(a2, a3));
    const float mn = fminf(a1, fminf(a2, a3));
    return sqrtf(mn / mx);
}

__global__ __launch_bounds__(128)
void curvature_kernel(const float* __restrict__ depth, float* __restrict__ out)
{
    int idx = blockIdx.x * blockDim.x + threadIdx.x;
    if (idx >= NPATCH) return;
    const int pi = idx >> 7;
    const int pj = idx & 127;

    const int yc = 8 * pi + 3, xc = 8 * pj + 3;
    const float d36 = __ldg(&depth[yc * IMG + xc]);

    float S[21], E[18];
    float T00, T01, T02, T11, T12, T22;

    if (pi > 0 && pj > 0) {
        // ======== interior fast path: grid moments are compile-time constants ========
        // data-dependent moments: Zk_ab = sum p1^a p2^b z^k, z = depth - d36
        float Z1_00=0.f,Z1_10=0.f,Z1_01=0.f,Z1_20=0.f,Z1_11=0.f,Z1_02=0.f;
        float Z1_30=0.f,Z1_21=0.f,Z1_12=0.f,Z1_03=0.f;
        float Z2_00=0.f,Z2_10=0.f,Z2_01=0.f,Z2_20=0.f,Z2_11=0.f,Z2_02=0.f;
        float Z3_00=0.f,Z3_10=0.f,Z3_01=0.f;
        float Z4_00=0.f;

        const int base = (8 * pi - 1) * IMG + (8 * pj - 1);
        #pragma unroll
        for (int r = 0; r < 8; r++) {
            const float B = (float)(r - 4);
            const float B2 = B * B, B3 = B2 * B;
            #pragma unroll
            for (int c = 0; c < 8; c++) {
                const float A = (float)(c - 4);
                const float A2 = A * A, A3 = A2 * A;
                const float z = __ldg(&depth[base + r * IMG + c]) - d36;
                const float z2 = z * z, z3 = z2 * z, z4 = z2 * z2;
                Z1_00 += z;
                Z1_10 += A * z;        Z1_01 += B * z;
                Z1_20 += A2 * z;       Z1_11 += (A * B) * z;     Z1_02 += B2 * z;
                Z1_30 += A3 * z;       Z1_21 += (A2 * B) * z;
                Z1_12 += (A * B2) * z; Z1_03 += B3 * z;
                Z2_00 += z2;
                Z2_10 += A * z2;       Z2_01 += B * z2;
                Z2_20 += A2 * z2;      Z2_11 += (A * B) * z2;    Z2_02 += B2 * z2;
                Z3_00 += z3;
                Z3_10 += A * z3;       Z3_01 += B * z3;
                Z4_00 += z4;
            }
        }
        // grid constants (s0=8, s1=-4, s2=44, s3=-64, s4=452):
        // G40=G04=3616, G22=1936, G31=G13=256, G30=G03=-512, G21=G12=-176,
        // G20=G02=352, G11=16
        S[0]  = 3616.f;          // f0f0 = sum p1^4
        S[1]  = 1936.f;          // f0f1
        S[2]  = Z2_20;           // f0f2
        S[3]  = 512.f;           // f0f3 = 2*G31
        S[4]  = 2.f * Z1_30;     // f0f4
        S[5]  = 2.f * Z1_21;     // f0f5
        S[6]  = 3616.f;          // f1f1
        S[7]  = Z2_02;           // f1f2
        S[8]  = 512.f;           // f1f3
        S[9]  = 2.f * Z1_12;     // f1f4
        S[10] = 2.f * Z1_03;     // f1f5
        S[11] = Z4_00;           // f2f2
        S[12] = 2.f * Z2_11;     // f2f3
        S[13] = 2.f * Z3_10;     // f2f4
        S[14] = 2.f * Z3_01;     // f2f5
        S[15] = 7744.f;          // f3f3 = 4*G22
        S[16] = 4.f * Z1_21;     // f3f4
        S[17] = 4.f * Z1_12;     // f3f5
        S[18] = 4.f * Z2_20;     // f4f4
        S[19] = 4.f * Z2_11;     // f4f5
        S[20] = 4.f * Z2_02;     // f5f5

        E[0]  = -1024.f;         // f0 l0 = 2*G30
        E[1]  = -352.f;          // f0 l1 = 2*G21
        E[2]  = 2.f * Z1_20;     // f0 l2
        E[3]  = -352.f;          // f1 l0
        E[4]  = -1024.f;         // f1 l1
        E[5]  = 2.f * Z1_02;     // f1 l2
        E[6]  = 2.f * Z2_10;     // f2 l0
        E[7]  = 2.f * Z2_01;     // f2 l1
        E[8]  = 2.f * Z3_00;     // f2 l2
        E[9]  = -704.f;          // f3 l0 = 4*G21
        E[10] = -704.f;          // f3 l1
        E[11] = 4.f * Z1_11;     // f3 l2
        E[12] = 4.f * Z1_20;     // f4 l0
        E[13] = 4.f * Z1_11;     // f4 l1
        E[14] = 4.f * Z2_10;     // f4 l2
        E[15] = 4.f * Z1_11;     // f5 l0
        E[16] = 4.f * Z1_02;     // f5 l1
        E[17] = 4.f * Z2_01;     // f5 l2

        T00 = 1408.f;            // 4*G20
        T01 = 64.f;              // 4*G11
        T02 = 4.f * Z1_10;
        T11 = 1408.f;
        T12 = 4.f * Z1_01;
        T22 = 4.f * Z2_00;
    } else {
        // ======== boundary path (255 patches): generic fp32 accumulation ========
        const float x36 = (float)xc, y36 = (float)yc;
        #pragma unroll
        for (int t = 0; t < 21; t++) S[t] = 0.f;
        #pragma unroll
        for (int t = 0; t < 18; t++) E[t] = 0.f;
        T00 = T01 = T02 = T11 = T12 = T22 = 0.f;

        #pragma unroll 1
        for (int r = 0; r < 8; r++) {
            const int R = 8 * pi + r;
            #pragma unroll
            for (int c = 0; c < 8; c++) {
                const int C = 8 * pj + c;
                float xv, yv, dv;
                if (R == 0 || C == 0) { xv = 0.f; yv = 0.f; dv = 0.f; }
                else {
                    xv = (float)(C - 1);
                    yv = (float)(R - 1);
                    dv = __ldg(&depth[(R - 1) * IMG + (C - 1)]);
                }
                const float p1 = xv - x36, p2 = yv - y36, p3 = dv - d36;
                float dd[6];
                dd[0] = p1 * p1; dd[1] = p2 * p2; dd[2] = p3 * p3;
                dd[3] = 2.f * p1 * p2; dd[4] = 2.f * p1 * p3; dd[5] = 2.f * p2 * p3;
                const float l0 = 2.f * p1, l1 = 2.f * p2, l2 = 2.f * p3;
                int t = 0;
                #pragma unroll
                for (int f = 0; f < 6; f++) {
                    #pragma unroll
                    for (int g = f; g < 6; g++) { S[t] += dd[f] * dd[g]; t++; }
                }
                #pragma unroll
                for (int f = 0; f < 6; f++) {
                    E[f * 3 + 0] += dd[f] * l0;
                    E[f * 3 + 1] += dd[f] * l1;
                    E[f * 3 + 2] += dd[f] * l2;
                }
                T00 += l0 * l0; T01 += l0 * l1; T02 += l0 * l2;
                T11 += l1 * l1; T12 += l1 * l2; T22 += l2 * l2;
            }
        }
    }

    out[idx] = solve_tail(S, E, T00, T01, T02, T11, T12, T22);
}

extern "C" void kernel_launch(void* const* d_in, const int* in_sizes, int n_in,
                              void* d_out, int out_size)
{
    const float* depth = (const float*)d_in[0];
    float* out = (float*)d_out;
    curvature_kernel<<<NPATCH / 128, 128>>>(depth, out);
}

// round 5
// speedup vs baseline: 2.6270x; 1.9064x over previous
#include <cuda_runtime.h>
#include <math.h>

#define IMG 1024
#define NPATCH 16384

__global__ __launch_bounds__(128)
void curvature_kernel(const float* __restrict__ depth, float* __restrict__ out)
{
    const int t = blockIdx.x * 128 + threadIdx.x;
    if (t >= NPATCH) return;

    // ---- thread->patch remap: interior patches first, boundary in last warps ----
    int pi, pj;
    const bool interior = (t < 127 * 127);
    if (interior) {
        const int r = t / 127;
        pi = 1 + r;
        pj = 1 + (t - r * 127);
    } else {
        const int b = t - 127 * 127;
        if (b < 128) { pi = 0; pj = b; }
        else { pi = b - 127; pj = 0; }
    }

    const int yc = 8 * pi + 3, xc = 8 * pj + 3;
    const float d36 = __ldg(&depth[yc * IMG + xc]);

    float S[21], E[18];
    float T00, T01, T02, T11, T12, T22;

    if (interior) {
        // ======== interior: grid moments are compile-time constants ========
        float Z1_10=0.f,Z1_01=0.f,Z1_20=0.f,Z1_11=0.f,Z1_02=0.f;
        float Z1_30=0.f,Z1_21=0.f,Z1_12=0.f,Z1_03=0.f;
        float Z2_00=0.f,Z2_10=0.f,Z2_01=0.f,Z2_20=0.f,Z2_11=0.f,Z2_02=0.f;
        float Z3_00=0.f,Z3_10=0.f,Z3_01=0.f;
        float Z4_00=0.f;

        const int base = (8 * pi - 1) * IMG + (8 * pj - 1);
        #pragma unroll
        for (int r = 0; r < 8; r++) {
            const float B = (float)(r - 4);
            const float B2 = B * B, B3 = B2 * B;
            #pragma unroll
            for (int c = 0; c < 8; c++) {
                const float A = (float)(c - 4);
                const float A2 = A * A, A3 = A2 * A;
                const float z = __ldg(&depth[base + r * IMG + c]) - d36;
                const float z2 = z * z, z3 = z2 * z, z4 = z2 * z2;
                Z1_10 += A * z;        Z1_01 += B * z;
                Z1_20 += A2 * z;       Z1_11 += (A * B) * z;     Z1_02 += B2 * z;
                Z1_30 += A3 * z;       Z1_21 += (A2 * B) * z;
                Z1_12 += (A * B2) * z; Z1_03 += B3 * z;
                Z2_00 += z2;
                Z2_10 += A * z2;       Z2_01 += B * z2;
                Z2_20 += A2 * z2;      Z2_11 += (A * B) * z2;    Z2_02 += B2 * z2;
                Z3_00 += z3;
                Z3_10 += A * z3;       Z3_01 += B * z3;
                Z4_00 += z4;
            }
        }
        S[0]  = 3616.f;        S[1]  = 1936.f;        S[2]  = Z2_20;
        S[3]  = 512.f;         S[4]  = 2.f * Z1_30;   S[5]  = 2.f * Z1_21;
        S[6]  = 3616.f;        S[7]  = Z2_02;         S[8]  = 512.f;
        S[9]  = 2.f * Z1_12;   S[10] = 2.f * Z1_03;   S[11] = Z4_00;
        S[12] = 2.f * Z2_11;   S[13] = 2.f * Z3_10;   S[14] = 2.f * Z3_01;
        S[15] = 7744.f;        S[16] = 4.f * Z1_21;   S[17] = 4.f * Z1_12;
        S[18] = 4.f * Z2_20;   S[19] = 4.f * Z2_11;   S[20] = 4.f * Z2_02;

        E[0]  = -1024.f;       E[1]  = -352.f;        E[2]  = 2.f * Z1_20;
        E[3]  = -352.f;        E[4]  = -1024.f;       E[5]  = 2.f * Z1_02;
        E[6]  = 2.f * Z2_10;   E[7]  = 2.f * Z2_01;   E[8]  = 2.f * Z3_00;
        E[9]  = -704.f;        E[10] = -704.f;        E[11] = 4.f * Z1_11;
        E[12] = 4.f * Z1_20;   E[13] = 4.f * Z1_11;   E[14] = 4.f * Z2_10;
        E[15] = 4.f * Z1_11;   E[16] = 4.f * Z1_02;   E[17] = 4.f * Z2_01;

        T00 = 1408.f;  T01 = 64.f;  T02 = 4.f * Z1_10;
        T11 = 1408.f;  T12 = 4.f * Z1_01;  T22 = 4.f * Z2_00;
    } else {
        // ======== boundary (255 patches, isolated into last warps) ========
        const float x36 = (float)xc, y36 = (float)yc;
        #pragma unroll
        for (int q = 0; q < 21; q++) S[q] = 0.f;
        #pragma unroll
        for (int q = 0; q < 18; q++) E[q] = 0.f;
        T00 = T01 = T02 = T11 = T12 = T22 = 0.f;

        #pragma unroll 1
        for (int r = 0; r < 8; r++) {
            const int R = 8 * pi + r;
            #pragma unroll
            for (int c = 0; c < 8; c++) {
                const int C = 8 * pj + c;
                float xv, yv, dv;
                if (R == 0 || C == 0) { xv = 0.f; yv = 0.f; dv = 0.f; }
                else {
                    xv = (float)(C - 1);
                    yv = (float)(R - 1);
                    dv = __ldg(&depth[(R - 1) * IMG + (C - 1)]);
                }
                const float p1 = xv - x36, p2 = yv - y36, p3 = dv - d36;
                float dd[6];
                dd[0] = p1 * p1; dd[1] = p2 * p2; dd[2] = p3 * p3;
                dd[3] = 2.f * p1 * p2; dd[4] = 2.f * p1 * p3; dd[5] = 2.f * p2 * p3;
                const float l0 = 2.f * p1, l1 = 2.f * p2, l2 = 2.f * p3;
                int tt2 = 0;
                #pragma unroll
                for (int f = 0; f < 6; f++) {
                    #pragma unroll
                    for (int g2 = f; g2 < 6; g2++) { S[tt2] += dd[f] * dd[g2]; tt2++; }
                }
                #pragma unroll
                for (int f = 0; f < 6; f++) {
                    E[f * 3 + 0] += dd[f] * l0;
                    E[f * 3 + 1] += dd[f] * l1;
                    E[f * 3 + 2] += dd[f] * l2;
                }
                T00 += l0 * l0; T01 += l0 * l1; T02 += l0 * l2;
                T11 += l1 * l1; T12 += l1 * l2; T22 += l2 * l2;
            }
        }
    }

    // ---- T^{-1} (3x3 symmetric) ----
    const float c00 = T11 * T22 - T12 * T12;
    const float c01 = T02 * T12 - T01 * T22;
    const float c02 = T01 * T12 - T02 * T11;
    const float det = T00 * c00 + T01 * c01 + T02 * c02;
    const float id = 1.0f / det;
    const float I00 = c00 * id, I01 = c01 * id, I02 = c02 * id;
    const float I11 = (T00 * T22 - T02 * T02) * id;
    const float I12 = (T01 * T02 - T00 * T12) * id;
    const float I22 = (T00 * T11 - T01 * T01) * id;

    // ---- A = S11 - E T^{-1} E^T ----
    float a[36];
    {
        int q = 0;
        #pragma unroll
        for (int f = 0; f < 6; f++) {
            const float e0 = E[f * 3 + 0], e1 = E[f * 3 + 1], e2 = E[f * 3 + 2];
            const float w0 = e0 * I00 + e1 * I01 + e2 * I02;
            const float w1 = e0 * I01 + e1 * I11 + e2 * I12;
            const float w2 = e0 * I02 + e1 * I12 + e2 * I22;
            #pragma unroll
            for (int g2 = f; g2 < 6; g2++) {
                const float v = S[q] - (w0 * E[g2 * 3 + 0] + w1 * E[g2 * 3 + 1] + w2 * E[g2 * 3 + 2]);
                a[f * 6 + g2] = v; a[g2 * 6 + f] = v; q++;
            }
        }
    }
    const float trA = a[0] + a[7] + a[14] + a[21] + a[28] + a[35];

    // ---- Cholesky A = L L^T ----
    float L[36];
    #pragma unroll
    for (int q = 0; q < 36; q++) L[q] = 0.0f;
    #pragma unroll
    for (int k = 0; k < 6; k++) {
        float s = a[k * 6 + k];
        #pragma unroll
        for (int m = 0; m < k; m++) s -= L[k * 6 + m] * L[k * 6 + m];
        s = fmaxf(s, fabsf(trA) * 1e-7f + 1e-30f);
        const float dk = sqrtf(s);
        const float inv = 1.0f / dk;
        L[k * 6 + k] = dk;
        #pragma unroll
        for (int r2 = k + 1; r2 < 6; r2++) {
            float sv = a[r2 * 6 + k];
            #pragma unroll
            for (int m = 0; m < k; m++) sv -= L[r2 * 6 + m] * L[k * 6 + m];
            L[r2 * 6 + k] = sv * inv;
        }
    }

    // ---- G = L^T Cinv L ----
    float g[36], g0[36];
    {
        float Y[36];
        #pragma unroll
        for (int j = 0; j < 6; j++) {
            Y[0 * 6 + j] = 0.5f * (L[6 + j] + L[12 + j]);
            Y[1 * 6 + j] = 0.5f * (L[0 + j] + L[12 + j]);
            Y[2 * 6 + j] = 0.5f * (L[0 + j] + L[6 + j]);
            Y[3 * 6 + j] = -0.25f * L[18 + j];
            Y[4 * 6 + j] = -0.25f * L[24 + j];
            Y[5 * 6 + j] = -0.25f * L[30 + j];
        }
        #pragma unroll
        for (int i2 = 0; i2 < 6; i2++) {
            #pragma unroll
            for (int j = 0; j < 6; j++) {
                float sv = 0.0f;
                #pragma unroll
                for (int k = 0; k < 6; k++) sv += L[k * 6 + i2] * Y[k * 6 + j];
                g[i2 * 6 + j] = sv;
                g0[i2 * 6 + j] = sv;
            }
        }
    }

    // ---- parallel-cyclic Jacobi, eigenvalues only: 4 sweeps x 5 rounds x 3 disjoint pairs ----
    #pragma unroll 1
    for (int sweep = 0; sweep < 4; sweep++) {
        #pragma unroll
        for (int rd = 0; rd < 5; rd++) {
            const int JP[5][3] = {{0,1,2},{0,3,1},{0,2,1},{0,1,4},{0,2,3}};
            const int JQ[5][3] = {{5,4,3},{4,5,2},{3,4,5},{2,3,5},{1,5,4}};
            float cc[3], ss[3];
            #pragma unroll
            for (int i = 0; i < 3; i++) {
                const int p = JP[rd][i], q = JQ[rd][i];
                const float apq = g[p * 6 + q];
                float tt = 0.0f;
                if (fabsf(apq) > 1e-37f) {
                    const float theta = (g[q * 7] - g[p * 7]) / (2.0f * apq);
                    tt = copysignf(1.0f, theta) / (fabsf(theta) + sqrtf(fmaf(theta, theta, 1.0f)));
                }
                const float cph = rsqrtf(fmaf(tt, tt, 1.0f));
                cc[i] = cph; ss[i] = tt * cph;
            }
            // column rotations (G J)
            #pragma unroll
            for (int i = 0; i < 3; i++) {
                const int p = JP[rd][i], q = JQ[rd][i];
                #pragma unroll
                for (int k = 0; k < 6; k++) {
                    const float a1 = g[k * 6 + p], a2 = g[k * 6 + q];
                    g[k * 6 + p] = cc[i] * a1 - ss[i] * a2;
                    g[k * 6 + q] = ss[i] * a1 + cc[i] * a2;
                }
            }
            // row rotations (J^T (G J))
            #pragma unroll
            for (int i = 0; i < 3; i++) {
                const int p = JP[rd][i], q = JQ[rd][i];
                #pragma unroll
                for (int k = 0; k < 6; k++) {
                    const float a1 = g[p * 6 + k], a2 = g[q * 6 + k];
                    g[p * 6 + k] = cc[i] * a1 - ss[i] * a2;
                    g[q * 6 + k] = ss[i] * a1 + cc[i] * a2;
                }
            }
        }
    }

    // ---- lam1 = unique positive eigenvalue = max diagonal ----
    float lam = g[0];
    #pragma unroll
    for (int d2 = 1; d2 < 6; d2++) lam = fmaxf(lam, g[d2 * 7]);

    // ---- eigenvector via inverse iteration with FAT shift (gap to other eigs is huge) ----
    const float scale = fabsf(g0[0]) + fabsf(g0[7]) + fabsf(g0[14]) +
                        fabsf(g0[21]) + fabsf(g0[28]) + fabsf(g0[35]);
    const float sig = lam + 3e-4f * scale + 1e-30f;   // H = sig*I - G guaranteed PD

    float Hc[36], rH[6];
    #pragma unroll
    for (int q = 0; q < 36; q++) Hc[q] = 0.0f;
    #pragma unroll
    for (int k = 0; k < 6; k++) {
        float s = sig - g0[k * 7];
        #pragma unroll
        for (int m = 0; m < k; m++) s -= Hc[k * 6 + m] * Hc[k * 6 + m];
        s = fmaxf(s, 1e-8f * scale + 1e-34f);
        const float dk = sqrtf(s);
        const float inv = 1.0f / dk;
        Hc[k * 6 + k] = dk;
        rH[k] = inv;
        #pragma unroll
        for (int r2 = k + 1; r2 < 6; r2++) {
            float sv = -g0[r2 * 6 + k];
            #pragma unroll
            for (int m = 0; m < k; m++) sv -= Hc[r2 * 6 + m] * Hc[k * 6 + m];
            Hc[r2 * 6 + k] = sv * inv;
        }
    }

    float x[6] = {1.0f, 0.81f, -0.65f, 0.43f, -0.29f, 0.17f};
    #pragma unroll
    for (int it = 0; it < 3; it++) {
        float y[6];
        #pragma unroll
        for (int k = 0; k < 6; k++) {
            float s = x[k];
            #pragma unroll
            for (int m = 0; m < k; m++) s -= Hc[k * 6 + m] * y[m];
            y[k] = s * rH[k];
        }
        #pragma unroll
        for (int k = 5; k >= 0; k--) {
            float s = y[k];
            #pragma unroll
            for (int m = 5; m > k; m--) s -= Hc[m * 6 + k] * x[m];
            x[k] = s * rH[k];
        }
        float nrm = x[0]*x[0]+x[1]*x[1]+x[2]*x[2]+x[3]*x[3]+x[4]*x[4]+x[5]*x[5];
        if (!(nrm > 0.0f && nrm < 3e37f)) {   // safety net: reset (should never fire)
            x[0] = 1.0f; x[1] = 0.81f; x[2] = -0.65f;
            x[3] = 0.43f; x[4] = -0.29f; x[5] = 0.17f;
            nrm = x[0]*x[0]+x[1]*x[1]+x[2]*x[2]+x[3]*x[3]+x[4]*x[4]+x[5]*x[5];
        }
        const float rn = rsqrtf(nrm);
        #pragma unroll
        for (int k = 0; k < 6; k++) x[k] *= rn;
    }

    // ---- back-substitution L^T v = x ----
    float v[6];
    #pragma unroll
    for (int k = 5; k >= 0; k--) {
        float s = x[k];
        #pragma unroll
        for (int m = 5; m > k; m--) s -= L[m * 6 + k] * v[m];
        v[k] = s / L[k * 6 + k];
    }

    // ---- closed-form symmetric 3x3 eigenvalues of Q ----
    const float qa = v[0], qb = v[1], qc = v[2], qd = v[3], qe = v[4], qf = v[5];
    float l1, l2, l3;
    const float off2 = qd * qd + qe * qe + qf * qf;
    if (off2 < 1e-30f) { l1 = qa; l2 = qb; l3 = qc; }
    else {
        const float qm = (qa + qb + qc) * (1.0f / 3.0f);
        const float aa = qa - qm, bb = qb - qm, cc2 = qc - qm;
        const float p2 = aa * aa + bb * bb + cc2 * cc2 + 2.0f * off2;
        const float p = sqrtf(p2 * (1.0f / 6.0f));
        const float ip = 1.0f / p;
        const float b00 = aa * ip, b11 = bb * ip, b22 = cc2 * ip;
        const float b01 = qd * ip, b02 = qe * ip, b12 = qf * ip;
        float detB = b00 * (b11 * b22 - b12 * b12)
                   - b01 * (b01 * b22 - b12 * b02)
                   + b02 * (b01 * b12 - b11 * b02);
        float rr = 0.5f * detB;
        rr = fminf(1.0f, fmaxf(-1.0f, rr));
        const float phi = acosf(rr) * (1.0f / 3.0f);
        l1 = qm + 2.0f * p * cosf(phi);
        l3 = qm + 2.0f * p * cosf(phi + 2.0943951023931953f);
        l2 = 3.0f * qm - l1 - l3;
    }
    const float a1 = fabsf(l1), a2 = fabsf(l2), a3 = fabsf(l3);
    const float mx = fmaxf(a1, fmaxf(a2, a3));
    const float mn = fminf(a1, fminf(a2, a3));
    out[pi * 128 + pj] = sqrtf(mn / mx);
}

extern "C" void kernel_launch(void* const* d_in, const int* in_sizes, int n_in,
                              void* d_out, int out_size)
{
    const float* depth = (const float*)d_in[0];
    float* out = (float*)d_out;
    curvature_kernel<<<NPATCH / 128, 128>>>(depth, out);
}

// round 6
// speedup vs baseline: 3.2153x; 1.2240x over previous
#include <cuda_runtime.h>
#include <math.h>

#define IMG 1024
#define NPATCH 16384

// canonical (upper-triangle) index into a 6x6 symmetric matrix stored in [36]
#define GIX(i,j) (((i)<(j)) ? ((i)*6+(j)) : ((j)*6+(i)))

__global__ __launch_bounds__(128)
void curvature_kernel(const float* __restrict__ depth, float* __restrict__ out)
{
    const int t = blockIdx.x * 128 + threadIdx.x;
    if (t >= NPATCH) return;

    // ---- thread->patch remap: interior patches first, boundary in last warps ----
    int pi, pj;
    const bool interior = (t < 127 * 127);
    if (interior) {
        const int r = t / 127;
        pi = 1 + r;
        pj = 1 + (t - r * 127);
    } else {
        const int b = t - 127 * 127;
        if (b < 128) { pi = 0; pj = b; }
        else { pi = b - 127; pj = 0; }
    }

    const int yc = 8 * pi + 3, xc = 8 * pj + 3;
    const float d36 = __ldg(&depth[yc * IMG + xc]);

    float S[21], E[18];
    float T00, T01, T02, T11, T12, T22;

    if (interior) {
        // ======== interior: grid moments are compile-time constants ========
        float Z1_10=0.f,Z1_01=0.f,Z1_20=0.f,Z1_11=0.f,Z1_02=0.f;
        float Z1_30=0.f,Z1_21=0.f,Z1_12=0.f,Z1_03=0.f;
        float Z2_00=0.f,Z2_10=0.f,Z2_01=0.f,Z2_20=0.f,Z2_11=0.f,Z2_02=0.f;
        float Z3_00=0.f,Z3_10=0.f,Z3_01=0.f;
        float Z4_00=0.f;

        const int base = (8 * pi - 1) * IMG + (8 * pj - 1);
        #pragma unroll
        for (int r = 0; r < 8; r++) {
            const float B = (float)(r - 4);
            const float B2 = B * B, B3 = B2 * B;
            #pragma unroll
            for (int c = 0; c < 8; c++) {
                const float A = (float)(c - 4);
                const float A2 = A * A, A3 = A2 * A;
                const float z = __ldg(&depth[base + r * IMG + c]) - d36;
                const float z2 = z * z, z3 = z2 * z, z4 = z2 * z2;
                Z1_10 += A * z;        Z1_01 += B * z;
                Z1_20 += A2 * z;       Z1_11 += (A * B) * z;     Z1_02 += B2 * z;
                Z1_30 += A3 * z;       Z1_21 += (A2 * B) * z;
                Z1_12 += (A * B2) * z; Z1_03 += B3 * z;
                Z2_00 += z2;
                Z2_10 += A * z2;       Z2_01 += B * z2;
                Z2_20 += A2 * z2;      Z2_11 += (A * B) * z2;    Z2_02 += B2 * z2;
                Z3_00 += z3;
                Z3_10 += A * z3;       Z3_01 += B * z3;
                Z4_00 += z4;
            }
        }
        S[0]  = 3616.f;        S[1]  = 1936.f;        S[2]  = Z2_20;
        S[3]  = 512.f;         S[4]  = 2.f * Z1_30;   S[5]  = 2.f * Z1_21;
        S[6]  = 3616.f;        S[7]  = Z2_02;         S[8]  = 512.f;
        S[9]  = 2.f * Z1_12;   S[10] = 2.f * Z1_03;   S[11] = Z4_00;
        S[12] = 2.f * Z2_11;   S[13] = 2.f * Z3_10;   S[14] = 2.f * Z3_01;
        S[15] = 7744.f;        S[16] = 4.f * Z1_21;   S[17] = 4.f * Z1_12;
        S[18] = 4.f * Z2_20;   S[19] = 4.f * Z2_11;   S[20] = 4.f * Z2_02;

        E[0]  = -1024.f;       E[1]  = -352.f;        E[2]  = 2.f * Z1_20;
        E[3]  = -352.f;        E[4]  = -1024.f;       E[5]  = 2.f * Z1_02;
        E[6]  = 2.f * Z2_10;   E[7]  = 2.f * Z2_01;   E[8]  = 2.f * Z3_00;
        E[9]  = -704.f;        E[10] = -704.f;        E[11] = 4.f * Z1_11;
        E[12] = 4.f * Z1_20;   E[13] = 4.f * Z1_11;   E[14] = 4.f * Z2_10;
        E[15] = 4.f * Z1_11;   E[16] = 4.f * Z1_02;   E[17] = 4.f * Z2_01;

        T00 = 1408.f;  T01 = 64.f;  T02 = 4.f * Z1_10;
        T11 = 1408.f;  T12 = 4.f * Z1_01;  T22 = 4.f * Z2_00;
    } else {
        // ======== boundary (255 patches, isolated into last warps) ========
        const float x36 = (float)xc, y36 = (float)yc;
        #pragma unroll
        for (int q = 0; q < 21; q++) S[q] = 0.f;
        #pragma unroll
        for (int q = 0; q < 18; q++) E[q] = 0.f;
        T00 = T01 = T02 = T11 = T12 = T22 = 0.f;

        #pragma unroll 1
        for (int r = 0; r < 8; r++) {
            const int R = 8 * pi + r;
            #pragma unroll
            for (int c = 0; c < 8; c++) {
                const int C = 8 * pj + c;
                float xv, yv, dv;
                if (R == 0 || C == 0) { xv = 0.f; yv = 0.f; dv = 0.f; }
                else {
                    xv = (float)(C - 1);
                    yv = (float)(R - 1);
                    dv = __ldg(&depth[(R - 1) * IMG + (C - 1)]);
                }
                const float p1 = xv - x36, p2 = yv - y36, p3 = dv - d36;
                float dd[6];
                dd[0] = p1 * p1; dd[1] = p2 * p2; dd[2] = p3 * p3;
                dd[3] = 2.f * p1 * p2; dd[4] = 2.f * p1 * p3; dd[5] = 2.f * p2 * p3;
                const float l0 = 2.f * p1, l1 = 2.f * p2, l2 = 2.f * p3;
                int tt2 = 0;
                #pragma unroll
                for (int f = 0; f < 6; f++) {
                    #pragma unroll
                    for (int g2 = f; g2 < 6; g2++) { S[tt2] += dd[f] * dd[g2]; tt2++; }
                }
                #pragma unroll
                for (int f = 0; f < 6; f++) {
                    E[f * 3 + 0] += dd[f] * l0;
                    E[f * 3 + 1] += dd[f] * l1;
                    E[f * 3 + 2] += dd[f] * l2;
                }
                T00 += l0 * l0; T01 += l0 * l1; T02 += l0 * l2;
                T11 += l1 * l1; T12 += l1 * l2; T22 += l2 * l2;
            }
        }
    }

    // ---- T^{-1} (3x3 symmetric) ----
    const float c00 = T11 * T22 - T12 * T12;
    const float c01 = T02 * T12 - T01 * T22;
    const float c02 = T01 * T12 - T02 * T11;
    const float det = T00 * c00 + T01 * c01 + T02 * c02;
    const float id = __fdividef(1.0f, det);
    const float I00 = c00 * id, I01 = c01 * id, I02 = c02 * id;
    const float I11 = (T00 * T22 - T02 * T02) * id;
    const float I12 = (T01 * T02 - T00 * T12) * id;
    const float I22 = (T00 * T11 - T01 * T01) * id;

    // ---- A = S11 - E T^{-1} E^T (upper triangle into full array) ----
    float a[36];
    {
        int q = 0;
        #pragma unroll
        for (int f = 0; f < 6; f++) {
            const float e0 = E[f * 3 + 0], e1 = E[f * 3 + 1], e2 = E[f * 3 + 2];
            const float w0 = e0 * I00 + e1 * I01 + e2 * I02;
            const float w1 = e0 * I01 + e1 * I11 + e2 * I12;
            const float w2 = e0 * I02 + e1 * I12 + e2 * I22;
            #pragma unroll
            for (int g2 = f; g2 < 6; g2++) {
                a[f * 6 + g2] = S[q] - (w0 * E[g2 * 3 + 0] + w1 * E[g2 * 3 + 1] + w2 * E[g2 * 3 + 2]);
                q++;
            }
        }
    }
    const float trA = a[0] + a[7] + a[14] + a[21] + a[28] + a[35];

    // ---- Cholesky A = L L^T  (fast-math sqrt/rcp) ----
    float L[36], rAL[6];
    #pragma unroll
    for (int q = 0; q < 36; q++) L[q] = 0.0f;
    #pragma unroll
    for (int k = 0; k < 6; k++) {
        float s = a[k * 6 + k];
        #pragma unroll
        for (int m = 0; m < k; m++) s -= L[k * 6 + m] * L[k * 6 + m];
        s = fmaxf(s, fabsf(trA) * 1e-7f + 1e-30f);
        const float rs = rsqrtf(s);
        L[k * 6 + k] = s * rs;        // sqrt(s)
        rAL[k] = rs;                  // 1/sqrt(s)
        #pragma unroll
        for (int r2 = k + 1; r2 < 6; r2++) {
            float sv = a[GIX(k, r2)];
            #pragma unroll
            for (int m = 0; m < k; m++) sv -= L[r2 * 6 + m] * L[k * 6 + m];
            L[r2 * 6 + k] = sv * rs;
        }
    }

    // ---- G = L^T Cinv L  (upper triangle only) ----
    float g[36], g0[36];
    {
        float Y[36];
        #pragma unroll
        for (int j = 0; j < 6; j++) {
            Y[0 * 6 + j] = 0.5f * (L[6 + j] + L[12 + j]);
            Y[1 * 6 + j] = 0.5f * (L[0 + j] + L[12 + j]);
            Y[2 * 6 + j] = 0.5f * (L[0 + j] + L[6 + j]);
            Y[3 * 6 + j] = -0.25f * L[18 + j];
            Y[4 * 6 + j] = -0.25f * L[24 + j];
            Y[5 * 6 + j] = -0.25f * L[30 + j];
        }
        #pragma unroll
        for (int i2 = 0; i2 < 6; i2++) {
            #pragma unroll
            for (int j = i2; j < 6; j++) {
                float sv = 0.0f;
                #pragma unroll
                for (int k = 0; k < 6; k++) sv += L[k * 6 + i2] * Y[k * 6 + j];
                g[i2 * 6 + j] = sv;
                g0[i2 * 6 + j] = sv;
            }
        }
    }

    // ---- symmetric-triangle parallel-cyclic Jacobi, 3 sweeps x 5 rounds x 3 disjoint pairs ----
    #pragma unroll 1
    for (int sweep = 0; sweep < 3; sweep++) {
        #pragma unroll
        for (int rd = 0; rd < 5; rd++) {
            const int JP[5][3] = {{0,1,2},{0,3,1},{0,2,1},{0,1,4},{0,2,3}};
            const int JQ[5][3] = {{5,4,3},{4,5,2},{3,4,5},{2,3,5},{1,5,4}};
            float tv[3], cv[3], sv3[3];
            #pragma unroll
            for (int i = 0; i < 3; i++) {
                const int p = JP[rd][i], q = JQ[rd][i];
                const float apq = g[p * 6 + q];
                float tt = 0.0f;
                if (fabsf(apq) > 1e-37f) {
                    const float theta = __fdividef(g[q * 7] - g[p * 7], 2.0f * apq);
                    const float u = fmaf(theta, theta, 1.0f);
                    tt = __fdividef(copysignf(1.0f, theta), fabsf(theta) + u * rsqrtf(u));
                }
                const float cph = rsqrtf(fmaf(tt, tt, 1.0f));
                tv[i] = tt; cv[i] = cph; sv3[i] = tt * cph;
            }
            // exact cheap updates (pivots/diagonals untouched by sibling rotations)
            #pragma unroll
            for (int i = 0; i < 3; i++) {
                const int p = JP[rd][i], q = JQ[rd][i];
                const float apq = g[p * 6 + q];
                g[p * 7] -= tv[i] * apq;
                g[q * 7] += tv[i] * apq;
                g[p * 6 + q] = 0.0f;
                #pragma unroll
                for (int k = 0; k < 6; k++) {
                    if (k != p && k != q) {
                        const float akp = g[GIX(k, p)], akq = g[GIX(k, q)];
                        g[GIX(k, p)] = cv[i] * akp - sv3[i] * akq;
                        g[GIX(k, q)] = sv3[i] * akp + cv[i] * akq;
                    }
                }
            }
        }
    }

    // ---- sigma = Gershgorin upper bound on lambda_max (guaranteed >= lam1) ----
    const float scale = fabsf(g0[0]) + fabsf(g0[7]) + fabsf(g0[14]) +
                        fabsf(g0[21]) + fabsf(g0[28]) + fabsf(g0[35]);
    float sig = -3e38f;
    #pragma unroll
    for (int i2 = 0; i2 < 6; i2++) {
        float row = g[i2 * 7];
        #pragma unroll
        for (int j = 0; j < 6; j++)
            if (j != i2) row += fabsf(g[GIX(i2, j)]);
        sig = fmaxf(sig, row);
    }
    sig += 1e-6f * scale + 1e-30f;

    // ---- H = sig*I - G0 (PD); Cholesky + 3 inverse iterations ----
    float Hc[36], rH[6];
    #pragma unroll
    for (int q = 0; q < 36; q++) Hc[q] = 0.0f;
    #pragma unroll
    for (int k = 0; k < 6; k++) {
        float s = sig - g0[k * 7];
        #pragma unroll
        for (int m = 0; m < k; m++) s -= Hc[k * 6 + m] * Hc[k * 6 + m];
        s = fmaxf(s, 1e-8f * scale + 1e-34f);
        const float rs = rsqrtf(s);
        Hc[k * 6 + k] = s * rs;
        rH[k] = rs;
        #pragma unroll
        for (int r2 = k + 1; r2 < 6; r2++) {
            float svv = -g0[GIX(k, r2)];
            #pragma unroll
            for (int m = 0; m < k; m++) svv -= Hc[r2 * 6 + m] * Hc[k * 6 + m];
            Hc[r2 * 6 + k] = svv * rs;
        }
    }

    float x[6] = {1.0f, 0.81f, -0.65f, 0.43f, -0.29f, 0.17f};
    #pragma unroll
    for (int it = 0; it < 3; it++) {
        float y[6];
        #pragma unroll
        for (int k = 0; k < 6; k++) {
            float s = x[k];
            #pragma unroll
            for (int m = 0; m < k; m++) s -= Hc[k * 6 + m] * y[m];
            y[k] = s * rH[k];
        }
        #pragma unroll
        for (int k = 5; k >= 0; k--) {
            float s = y[k];
            #pragma unroll
            for (int m = 5; m > k; m--) s -= Hc[m * 6 + k] * x[m];
            x[k] = s * rH[k];
        }
        float nrm = x[0]*x[0]+x[1]*x[1]+x[2]*x[2]+x[3]*x[3]+x[4]*x[4]+x[5]*x[5];
        if (!(nrm > 0.0f && nrm < 3e37f)) {   // safety net (deterministic reset)
            x[0] = 1.0f; x[1] = 0.81f; x[2] = -0.65f;
            x[3] = 0.43f; x[4] = -0.29f; x[5] = 0.17f;
            nrm = x[0]*x[0]+x[1]*x[1]+x[2]*x[2]+x[3]*x[3]+x[4]*x[4]+x[5]*x[5];
        }
        const float rn = rsqrtf(nrm);
        #pragma unroll
        for (int k = 0; k < 6; k++) x[k] *= rn;
    }

    // ---- back-substitution L^T v = x ----
    float v[6];
    #pragma unroll
    for (int k = 5; k >= 0; k--) {
        float s = x[k];
        #pragma unroll
        for (int m = 5; m > k; m--) s -= L[m * 6 + k] * v[m];
        v[k] = s * rAL[k];
    }

    // ---- closed-form symmetric 3x3 eigenvalues of Q ----
    const float qa = v[0], qb = v[1], qc = v[2], qd = v[3], qe = v[4], qf = v[5];
    float l1, l2, l3;
    const float off2 = qd * qd + qe * qe + qf * qf;
    if (off2 < 1e-30f) { l1 = qa; l2 = qb; l3 = qc; }
    else {
        const float qm = (qa + qb + qc) * (1.0f / 3.0f);
        const float aa = qa - qm, bb = qb - qm, cc2 = qc - qm;
        const float p2 = aa * aa + bb * bb + cc2 * cc2 + 2.0f * off2;
        const float p2s = p2 * (1.0f / 6.0f);
        const float rp = rsqrtf(p2s);
        const float p = p2s * rp;       // sqrt(p2/6)
        const float ip = rp;            // 1/p
        const float b00 = aa * ip, b11 = bb * ip, b22 = cc2 * ip;
        const float b01 = qd * ip, b02 = qe * ip, b12 = qf * ip;
        float detB = b00 * (b11 * b22 - b12 * b12)
                   - b01 * (b01 * b22 - b12 * b02)
                   + b02 * (b01 * b12 - b11 * b02);
        float rr = 0.5f * detB;
        rr = fminf(1.0f, fmaxf(-1.0f, rr));
        const float phi = acosf(rr) * (1.0f / 3.0f);
        l1 = qm + 2.0f * p * cosf(phi);
        l3 = qm + 2.0f * p * cosf(phi + 2.0943951023931953f);
        l2 = 3.0f * qm - l1 - l3;
    }
    const float a1 = fabsf(l1), a2 = fabsf(l2), a3 = fabsf(l3);
    const float mx = fmaxf(a1, fmaxf(a2, a3));
    const float mn = fminf(a1, fminf(a2, a3));
    out[pi * 128 + pj] = sqrtf(__fdividef(mn, mx));
}

extern "C" void kernel_launch(void* const* d_in, const int* in_sizes, int n_in,
                              void* d_out, int out_size)
{
    const float* depth = (const float*)d_in[0];
    float* out = (float*)d_out;
    curvature_kernel<<<NPATCH / 128, 128>>>(depth, out);
}